// round 6
// baseline (speedup 1.0000x reference)
#include <cuda_runtime.h>

typedef unsigned long long u64;

#define NN 100000
#define NE 1600000
#define EMBD 128
#define G1D 512
#define G2D 64000
#define DD 64
#define ECD 16
#define NB 100
#define NSCAN_BLKS 196

__device__ float g_h[NB * G1D];
__device__ float g_x[NN * DD];
__device__ float g_x2[NN * DD];
__device__ float g_y[NN * DD];
__device__ float g_agg[NN * DD];
__device__ int g_cnt[NN];
__device__ int g_rowptr[NN + 1];
__device__ int g_ofs[NN];
__device__ int g_bsum[NSCAN_BLKS];
__device__ int g_perm[NE];
__device__ int g_srcp[NE];
__device__ float g_eap[(u64)NE * ECD];

__device__ __forceinline__ u64 f2fma(u64 a, u64 b, u64 c) {
    u64 d;
    asm("fma.rn.f32x2 %0, %1, %2, %3;" : "=l"(d) : "l"(a), "l"(b), "l"(c));
    return d;
}
__device__ __forceinline__ u64 f2dup(float x) {
    u64 d;
    asm("mov.b64 %0, {%1, %2};" : "=l"(d) : "f"(x), "f"(x));
    return d;
}
__device__ __forceinline__ u64 f2pack(float x, float y) {
    u64 d;
    asm("mov.b64 %0, {%1, %2};" : "=l"(d) : "f"(x), "f"(y));
    return d;
}
__device__ __forceinline__ float2 f2unpack(u64 d) {
    float2 r;
    asm("mov.b64 {%0, %1}, %2;" : "=f"(r.x), "=f"(r.y) : "l"(d));
    return r;
}

__global__ __launch_bounds__(512) void k_mlp1(const float* __restrict__ emb,
                                              const float* __restrict__ W,
                                              const float* __restrict__ b) {
    __shared__ float sE[EMBD];
    int bid = blockIdx.x, tid = threadIdx.x;
    if (tid < EMBD) sE[tid] = emb[bid * EMBD + tid];
    __syncthreads();
    float acc = 0.f;
#pragma unroll 16
    for (int k = 0; k < EMBD; k++) acc += sE[k] * __ldg(&W[k * G1D + tid]);
    g_h[bid * G1D + tid] = fmaxf(acc + b[tid], 0.f);
}

__global__ __launch_bounds__(256) void k_mlp2(const float* __restrict__ W,
                                              const float* __restrict__ bias) {
    __shared__ __align__(16) u64 sA[16][128];
    __shared__ __align__(16) float sB[16][128];
    const float* h = g_h;
    int tid = threadIdx.x;
    int n0 = blockIdx.x * 128;
    int tx = tid & 15, ty = tid >> 4;
    int mb = ty * 8, cb = tx * 8;
    u64 acc[8][4];
#pragma unroll
    for (int r = 0; r < 8; r++)
#pragma unroll
        for (int c = 0; c < 4; c++) acc[r][c] = 0ull;
    int am = tid >> 1;
    int ak = (tid & 1) * 8;
    int bk = tid >> 4;
    int bn = (tid & 15) * 8;
    for (int k0 = 0; k0 < G1D; k0 += 16) {
        float4 a0 = make_float4(0.f, 0.f, 0.f, 0.f), a1 = a0;
        if (am < NB) {
            const float4* hp = reinterpret_cast<const float4*>(h + am * G1D + k0 + ak);
            a0 = hp[0];
            a1 = hp[1];
        }
        const float4* wp =
            reinterpret_cast<const float4*>(W + (u64)(k0 + bk) * G2D + n0 + bn);
        float4 b0 = wp[0], b1 = wp[1];
        __syncthreads();
        sA[ak + 0][am] = f2dup(a0.x);
        sA[ak + 1][am] = f2dup(a0.y);
        sA[ak + 2][am] = f2dup(a0.z);
        sA[ak + 3][am] = f2dup(a0.w);
        sA[ak + 4][am] = f2dup(a1.x);
        sA[ak + 5][am] = f2dup(a1.y);
        sA[ak + 6][am] = f2dup(a1.z);
        sA[ak + 7][am] = f2dup(a1.w);
        *reinterpret_cast<float4*>(&sB[bk][bn]) = b0;
        *reinterpret_cast<float4*>(&sB[bk][bn + 4]) = b1;
        __syncthreads();
#pragma unroll
        for (int k = 0; k < 16; k++) {
            const ulonglong2* ap = reinterpret_cast<const ulonglong2*>(&sA[k][mb]);
            ulonglong2 av0 = ap[0], av1 = ap[1], av2 = ap[2], av3 = ap[3];
            const ulonglong2* bp = reinterpret_cast<const ulonglong2*>(&sB[k][cb]);
            ulonglong2 bv0 = bp[0], bv1 = bp[1];
            u64 ar[8] = {av0.x, av0.y, av1.x, av1.y, av2.x, av2.y, av3.x, av3.y};
            u64 br[4] = {bv0.x, bv0.y, bv1.x, bv1.y};
#pragma unroll
            for (int r = 0; r < 8; r++)
#pragma unroll
                for (int c = 0; c < 4; c++) acc[r][c] = f2fma(ar[r], br[c], acc[r][c]);
        }
    }
    float2 bs[4];
#pragma unroll
    for (int c = 0; c < 4; c++)
        bs[c] = *reinterpret_cast<const float2*>(bias + n0 + cb + 2 * c);
#pragma unroll
    for (int r = 0; r < 8; r++) {
        int row = mb + r;
        if (row < NB) {
            float* op = g_x + (u64)row * G2D + n0 + cb;
#pragma unroll
            for (int c = 0; c < 4; c++) {
                float2 v = f2unpack(acc[r][c]);
                v.x += bs[c].x;
                v.y += bs[c].y;
                *reinterpret_cast<float2*>(op + 2 * c) = v;
            }
        }
    }
}

__global__ void k_zero_cnt() {
    int i = blockIdx.x * 256 + threadIdx.x;
    if (i < NN) g_cnt[i] = 0;
}
__global__ void k_hist(const int* __restrict__ ei) {
    int e = blockIdx.x * 256 + threadIdx.x;
    if (e < NE) atomicAdd(&g_cnt[__ldg(&ei[NE + e])], 1);
}
__global__ __launch_bounds__(512) void k_scan1() {
    __shared__ int s[512];
    int i = blockIdx.x * 512 + threadIdx.x;
    int v = (i < NN) ? g_cnt[i] : 0;
    s[threadIdx.x] = v;
    __syncthreads();
#pragma unroll
    for (int off = 1; off < 512; off <<= 1) {
        int t = (threadIdx.x >= off) ? s[threadIdx.x - off] : 0;
        __syncthreads();
        s[threadIdx.x] += t;
        __syncthreads();
    }
    if (i < NN) g_rowptr[i] = s[threadIdx.x] - v;
    if (threadIdx.x == 511) g_bsum[blockIdx.x] = s[511];
}
__global__ __launch_bounds__(256) void k_scan2() {
    __shared__ int s[256];
    int tid = threadIdx.x;
    int v = (tid < NSCAN_BLKS) ? g_bsum[tid] : 0;
    s[tid] = v;
    __syncthreads();
#pragma unroll
    for (int off = 1; off < 256; off <<= 1) {
        int t = (tid >= off) ? s[tid - off] : 0;
        __syncthreads();
        s[tid] += t;
        __syncthreads();
    }
    if (tid < NSCAN_BLKS) g_bsum[tid] = s[tid] - v;
}
__global__ void k_scan3() {
    int i = blockIdx.x * 256 + threadIdx.x;
    if (i < NN) {
        int r = g_rowptr[i] + g_bsum[i >> 9];
        g_rowptr[i] = r;
        g_ofs[i] = r;
    }
    if (i == 0) g_rowptr[NN] = NE;
}
__global__ void k_permute(const int* __restrict__ ei) {
    int e = blockIdx.x * 256 + threadIdx.x;
    if (e < NE) {
        int dst = __ldg(&ei[NE + e]);
        int pos = atomicAdd(&g_ofs[dst], 1);
        g_perm[pos] = e;
    }
}
__global__ __launch_bounds__(256) void k_gatherperm(const int* __restrict__ ei,
                                                    const float* __restrict__ ea) {
    int tid = threadIdx.x;
    int t = tid & 3;
    int pos = blockIdx.x * 64 + (tid >> 2);
    int eo = __ldg(&g_perm[pos]);
    if (t == 0) g_srcp[pos] = __ldg(&ei[eo]);
    float4 v = __ldg(reinterpret_cast<const float4*>(ea) + (u64)eo * 4 + t);
    reinterpret_cast<float4*>(g_eap)[(u64)pos * 4 + t] = v;
}

__global__ __launch_bounds__(128) void k_ynode(const float* __restrict__ x,
                                               const float* __restrict__ mW,
                                               const float* __restrict__ mb) {
    __shared__ float sX[64][65];
    __shared__ float sW[64][64];
    int tid = threadIdx.x;
    int node0 = blockIdx.x * 64;
    for (int i = tid; i < 64 * 64; i += 128) sW[i >> 6][i & 63] = mW[i];
    for (int i = tid; i < 64 * 64; i += 128) {
        int n = i >> 6, c = i & 63;
        int nn = node0 + n;
        if (nn >= NN) nn = NN - 1;
        sX[n][c] = x[(u64)nn * DD + c];
    }
    __syncthreads();
    int f0 = (tid & 7) * 8;
    int n0 = (tid >> 3) * 4;
    u64 acc[4][4];
#pragma unroll
    for (int j = 0; j < 4; j++)
#pragma unroll
        for (int c = 0; c < 4; c++) acc[j][c] = 0ull;
#pragma unroll 8
    for (int k = 0; k < 64; k++) {
        ulonglong2 w01 = *reinterpret_cast<const ulonglong2*>(&sW[k][f0]);
        ulonglong2 w23 = *reinterpret_cast<const ulonglong2*>(&sW[k][f0 + 4]);
#pragma unroll
        for (int j = 0; j < 4; j++) {
            u64 a = f2dup(sX[n0 + j][k]);
            acc[j][0] = f2fma(a, w01.x, acc[j][0]);
            acc[j][1] = f2fma(a, w01.y, acc[j][1]);
            acc[j][2] = f2fma(a, w23.x, acc[j][2]);
            acc[j][3] = f2fma(a, w23.y, acc[j][3]);
        }
    }
    float2 bv[4];
#pragma unroll
    for (int c = 0; c < 4; c++)
        bv[c] = *reinterpret_cast<const float2*>(mb + f0 + 2 * c);
#pragma unroll
    for (int j = 0; j < 4; j++) {
        int nn = node0 + n0 + j;
        if (nn < NN) {
            float o[8];
#pragma unroll
            for (int c = 0; c < 4; c++) {
                float2 v = f2unpack(acc[j][c]);
                o[2 * c] = v.x + bv[c].x;
                o[2 * c + 1] = v.y + bv[c].y;
            }
            float* yp = g_y + (u64)nn * DD + f0;
            *reinterpret_cast<float4*>(yp) = make_float4(o[0], o[1], o[2], o[3]);
            *reinterpret_cast<float4*>(yp + 4) = make_float4(o[4], o[5], o[6], o[7]);
        }
    }
}

// z for one edge given ea regs (a0..a3) — 16 f2fma, two chains
#define EDGE_Z(a0, a1, a2, a3, yv)                                               \
    {                                                                            \
        u64 z0 = 0ull, z1 = 0ull;                                                \
        z0 = f2fma(f2dup(a0.x), w[0], z0);  z1 = f2fma(f2dup(a0.y), w[1], z1);   \
        z0 = f2fma(f2dup(a0.z), w[2], z0);  z1 = f2fma(f2dup(a0.w), w[3], z1);   \
        z0 = f2fma(f2dup(a1.x), w[4], z0);  z1 = f2fma(f2dup(a1.y), w[5], z1);   \
        z0 = f2fma(f2dup(a1.z), w[6], z0);  z1 = f2fma(f2dup(a1.w), w[7], z1);   \
        z0 = f2fma(f2dup(a2.x), w[8], z0);  z1 = f2fma(f2dup(a2.y), w[9], z1);   \
        z0 = f2fma(f2dup(a2.z), w[10], z0); z1 = f2fma(f2dup(a2.w), w[11], z1);  \
        z0 = f2fma(f2dup(a3.x), w[12], z0); z1 = f2fma(f2dup(a3.y), w[13], z1);  \
        z0 = f2fma(f2dup(a3.z), w[14], z0); z1 = f2fma(f2dup(a3.w), w[15], z1);  \
        float2 za = f2unpack(z0), zb = f2unpack(z1);                             \
        accx += fmaxf(yv.x + za.x + zb.x, 0.f);                                  \
        accy += fmaxf(yv.y + za.y + zb.y, 0.f);                                  \
    }

__global__ __launch_bounds__(256) void k_agg(const float* __restrict__ mW) {
    __shared__ float2 sWe[16][32];
    int tid = threadIdx.x;
    for (int i = tid; i < 512; i += 256) {
        int k = i >> 5, l = i & 31;
        sWe[k][l] = *reinterpret_cast<const float2*>(mW + (64 + k) * DD + 2 * l);
    }
    __syncthreads();
    int lane = tid & 31;
    int node = blockIdx.x * 8 + (tid >> 5);
    u64 w[16];
#pragma unroll
    for (int k = 0; k < 16; k++) {
        float2 t = sWe[k][lane];
        w[k] = f2pack(t.x, t.y);
    }
    int e = g_rowptr[node], e_end = g_rowptr[node + 1];
    float accx = 0.f, accy = 0.f;
    // 4-edge unrolled main loop: 4 independent y-gathers in flight
    for (; e + 4 <= e_end; e += 4) {
        int s0 = __ldg(&g_srcp[e]);
        int s1 = __ldg(&g_srcp[e + 1]);
        int s2 = __ldg(&g_srcp[e + 2]);
        int s3 = __ldg(&g_srcp[e + 3]);
        float2 y0 = __ldg(reinterpret_cast<const float2*>(g_y + (u64)s0 * DD) + lane);
        float2 y1 = __ldg(reinterpret_cast<const float2*>(g_y + (u64)s1 * DD) + lane);
        float2 y2 = __ldg(reinterpret_cast<const float2*>(g_y + (u64)s2 * DD) + lane);
        float2 y3 = __ldg(reinterpret_cast<const float2*>(g_y + (u64)s3 * DD) + lane);
        const float4* p = reinterpret_cast<const float4*>(g_eap + (u64)e * ECD);
        {
            float4 a0 = __ldg(p + 0), a1 = __ldg(p + 1), a2 = __ldg(p + 2),
                   a3 = __ldg(p + 3);
            EDGE_Z(a0, a1, a2, a3, y0);
        }
        {
            float4 a0 = __ldg(p + 4), a1 = __ldg(p + 5), a2 = __ldg(p + 6),
                   a3 = __ldg(p + 7);
            EDGE_Z(a0, a1, a2, a3, y1);
        }
        {
            float4 a0 = __ldg(p + 8), a1 = __ldg(p + 9), a2 = __ldg(p + 10),
                   a3 = __ldg(p + 11);
            EDGE_Z(a0, a1, a2, a3, y2);
        }
        {
            float4 a0 = __ldg(p + 12), a1 = __ldg(p + 13), a2 = __ldg(p + 14),
                   a3 = __ldg(p + 15);
            EDGE_Z(a0, a1, a2, a3, y3);
        }
    }
    for (; e < e_end; e++) {
        int s0 = __ldg(&g_srcp[e]);
        const float4* p = reinterpret_cast<const float4*>(g_eap + (u64)e * ECD);
        float4 a0 = __ldg(p + 0), a1 = __ldg(p + 1), a2 = __ldg(p + 2),
               a3 = __ldg(p + 3);
        float2 y0 = __ldg(reinterpret_cast<const float2*>(g_y + (u64)s0 * DD) + lane);
        EDGE_Z(a0, a1, a2, a3, y0);
    }
    *reinterpret_cast<float2*>(g_agg + (u64)node * DD + 2 * lane) =
        make_float2(accx, accy);
}

#define UPD_SMEM (128 * 130 * 4 + 128 * 64 * 4)
__global__ __launch_bounds__(256) void k_update(const float* __restrict__ x,
                                                const float* __restrict__ uW,
                                                const float* __restrict__ ub,
                                                float* __restrict__ xo) {
    extern __shared__ float us[];
    float(*sIn)[130] = reinterpret_cast<float(*)[130]>(us);
    float(*sW)[64] = reinterpret_cast<float(*)[64]>(us + 128 * 130);
    int tid = threadIdx.x;
    int node0 = blockIdx.x * 128;
    for (int i = tid; i < 128 * 64; i += 256) sW[i >> 6][i & 63] = uW[i];
    for (int i = tid; i < 128 * 128; i += 256) {
        int n = i >> 7, c = i & 127;
        int nn = node0 + n;
        if (nn >= NN) nn = NN - 1;
        float v = (c < 64) ? x[(u64)nn * DD + c] : g_agg[(u64)nn * DD + c - 64];
        sIn[n][c] = v;
    }
    __syncthreads();
    int f0 = (tid & 7) * 8;
    int n0 = (tid >> 3) * 4;
    u64 acc[4][4];
#pragma unroll
    for (int j = 0; j < 4; j++)
#pragma unroll
        for (int c = 0; c < 4; c++) acc[j][c] = 0ull;
#pragma unroll 8
    for (int k = 0; k < 128; k++) {
        ulonglong2 w01 = *reinterpret_cast<const ulonglong2*>(&sW[k][f0]);
        ulonglong2 w23 = *reinterpret_cast<const ulonglong2*>(&sW[k][f0 + 4]);
#pragma unroll
        for (int j = 0; j < 4; j++) {
            u64 a = f2dup(sIn[n0 + j][k]);
            acc[j][0] = f2fma(a, w01.x, acc[j][0]);
            acc[j][1] = f2fma(a, w01.y, acc[j][1]);
            acc[j][2] = f2fma(a, w23.x, acc[j][2]);
            acc[j][3] = f2fma(a, w23.y, acc[j][3]);
        }
    }
    float2 bv[4];
#pragma unroll
    for (int c = 0; c < 4; c++)
        bv[c] = *reinterpret_cast<const float2*>(ub + f0 + 2 * c);
#pragma unroll
    for (int j = 0; j < 4; j++) {
        int nn = node0 + n0 + j;
        if (nn < NN) {
            float o[8];
#pragma unroll
            for (int c = 0; c < 4; c++) {
                float2 v = f2unpack(acc[j][c]);
                o[2 * c] = fmaxf(v.x + bv[c].x, 0.f);
                o[2 * c + 1] = fmaxf(v.y + bv[c].y, 0.f);
            }
            float* op = xo + (u64)nn * DD + f0;
            *reinterpret_cast<float4*>(op) = make_float4(o[0], o[1], o[2], o[3]);
            *reinterpret_cast<float4*>(op + 4) = make_float4(o[4], o[5], o[6], o[7]);
        }
    }
}

#define NM_SMEM (64 * 128 * 4 + 64 * 65 * 4 + 64 * 130 * 4 + 128 * 4 * 4)
__global__ __launch_bounds__(256) void k_nodemlp(const float* __restrict__ W1,
                                                 const float* __restrict__ b1,
                                                 const float* __restrict__ W2,
                                                 const float* __restrict__ b2,
                                                 float* __restrict__ out) {
    extern __shared__ float nsm[];
    float(*sW1)[128] = reinterpret_cast<float(*)[128]>(nsm);
    float(*sX)[65] = reinterpret_cast<float(*)[65]>(nsm + 64 * 128);
    float(*sH)[130] = reinterpret_cast<float(*)[130]>(nsm + 64 * 128 + 64 * 65);
    float(*sW2)[4] =
        reinterpret_cast<float(*)[4]>(nsm + 64 * 128 + 64 * 65 + 64 * 130);
    int tid = threadIdx.x;
    int node0 = blockIdx.x * 64;
    for (int i = tid; i < 64 * 128; i += 256) sW1[i >> 7][i & 127] = W1[i];
    if (tid < 128) {
        sW2[tid][0] = W2[tid * 3 + 0];
        sW2[tid][1] = W2[tid * 3 + 1];
        sW2[tid][2] = W2[tid * 3 + 2];
    }
    for (int i = tid; i < 64 * 64; i += 256) {
        int n = i >> 6, c = i & 63;
        int nn = node0 + n;
        if (nn >= NN) nn = NN - 1;
        sX[n][c] = g_x[(u64)nn * DD + c];
    }
    __syncthreads();
    int f0 = (tid & 15) * 8;
    int n0 = (tid >> 4) * 4;
    u64 acc[4][4];
#pragma unroll
    for (int j = 0; j < 4; j++)
#pragma unroll
        for (int c = 0; c < 4; c++) acc[j][c] = 0ull;
#pragma unroll 8
    for (int k = 0; k < 64; k++) {
        ulonglong2 w01 = *reinterpret_cast<const ulonglong2*>(&sW1[k][f0]);
        ulonglong2 w23 = *reinterpret_cast<const ulonglong2*>(&sW1[k][f0 + 4]);
#pragma unroll
        for (int j = 0; j < 4; j++) {
            u64 a = f2dup(sX[n0 + j][k]);
            acc[j][0] = f2fma(a, w01.x, acc[j][0]);
            acc[j][1] = f2fma(a, w01.y, acc[j][1]);
            acc[j][2] = f2fma(a, w23.x, acc[j][2]);
            acc[j][3] = f2fma(a, w23.y, acc[j][3]);
        }
    }
    float2 bv[4];
#pragma unroll
    for (int c = 0; c < 4; c++)
        bv[c] = *reinterpret_cast<const float2*>(b1 + f0 + 2 * c);
#pragma unroll
    for (int j = 0; j < 4; j++) {
#pragma unroll
        for (int c = 0; c < 4; c++) {
            float2 v = f2unpack(acc[j][c]);
            sH[n0 + j][f0 + 2 * c] = fmaxf(v.x + bv[c].x, 0.f);
            sH[n0 + j][f0 + 2 * c + 1] = fmaxf(v.y + bv[c].y, 0.f);
        }
    }
    __syncthreads();
    if (tid < 192) {
        int node = tid / 3, c = tid % 3;
        int nn = node0 + node;
        if (nn < NN) {
            float o = b2[c];
#pragma unroll 16
            for (int j = 0; j < 128; j++) o += sH[node][j] * sW2[j][c];
            out[(u64)nn * 3 + c] = o;
        }
    }
}

extern "C" void kernel_launch(void* const* d_in, const int* in_sizes, int n_in,
                              void* d_out, int out_size) {
    const float* emb = (const float*)d_in[0];
    const int* edge_index = (const int*)d_in[1];
    const float* edge_attr = (const float*)d_in[2];
    const float* Wg1 = (const float*)d_in[3];
    const float* bg1 = (const float*)d_in[4];
    const float* Wg2 = (const float*)d_in[5];
    const float* bg2 = (const float*)d_in[6];
    const float* mW0 = (const float*)d_in[7];
    const float* mb0 = (const float*)d_in[8];
    const float* uW0 = (const float*)d_in[9];
    const float* ub0 = (const float*)d_in[10];
    const float* mW1 = (const float*)d_in[11];
    const float* mb1 = (const float*)d_in[12];
    const float* uW1 = (const float*)d_in[13];
    const float* ub1 = (const float*)d_in[14];
    const float* nW1 = (const float*)d_in[15];
    const float* nb1 = (const float*)d_in[16];
    const float* nW2 = (const float*)d_in[17];
    const float* nb2 = (const float*)d_in[18];
    float* out = (float*)d_out;

    float *p_x, *p_x2;
    cudaGetSymbolAddress((void**)&p_x, g_x);
    cudaGetSymbolAddress((void**)&p_x2, g_x2);

    cudaFuncSetAttribute(k_update, cudaFuncAttributeMaxDynamicSharedMemorySize,
                         UPD_SMEM);
    cudaFuncSetAttribute(k_nodemlp, cudaFuncAttributeMaxDynamicSharedMemorySize,
                         NM_SMEM);

    // launch order arranged so the profiled launch (#3) is k_mlp2
    k_zero_cnt<<<(NN + 255) / 256, 256>>>();
    k_hist<<<(NE + 255) / 256, 256>>>(edge_index);
    k_mlp1<<<NB, 512>>>(emb, Wg1, bg1);
    k_mlp2<<<G2D / 128, 256>>>(Wg2, bg2);
    k_scan1<<<NSCAN_BLKS, 512>>>();
    k_scan2<<<1, 256>>>();
    k_scan3<<<(NN + 255) / 256, 256>>>();
    k_permute<<<(NE + 255) / 256, 256>>>(edge_index);
    k_gatherperm<<<NE / 64, 256>>>(edge_index, edge_attr);

    k_ynode<<<(NN + 63) / 64, 128>>>(p_x, mW0, mb0);
    k_agg<<<NN / 8, 256>>>(mW0);
    k_update<<<(NN + 127) / 128, 256, UPD_SMEM>>>(p_x, uW0, ub0, p_x2);
    k_ynode<<<(NN + 63) / 64, 128>>>(p_x2, mW1, mb1);
    k_agg<<<NN / 8, 256>>>(mW1);
    k_update<<<(NN + 127) / 128, 256, UPD_SMEM>>>(p_x2, uW1, ub1, p_x);
    k_nodemlp<<<(NN + 63) / 64, 256, NM_SMEM>>>(nW1, nb1, nW2, nb2, out);
}

// round 7
// speedup vs baseline: 1.0978x; 1.0978x over previous
#include <cuda_runtime.h>

typedef unsigned long long u64;

#define NN 100000
#define NE 1600000
#define EMBD 128
#define G1D 512
#define G2D 64000
#define DD 64
#define ECD 16
#define NB 100
#define NSCAN_BLKS 196

__device__ float g_h[NB * G1D];
__device__ float g_x[NN * DD];
__device__ float g_x2[NN * DD];
__device__ float g_y[NN * DD];
__device__ float g_agg[NN * DD];
__device__ int g_cnt[NN];
__device__ int g_rowptr[NN + 1];
__device__ int g_ofs[NN];
__device__ int g_bsum[NSCAN_BLKS];
__device__ int g_perm[NE];
__device__ int g_srcp[NE];
__device__ float g_eap[(u64)NE * ECD];

__device__ __forceinline__ u64 f2fma(u64 a, u64 b, u64 c) {
    u64 d;
    asm("fma.rn.f32x2 %0, %1, %2, %3;" : "=l"(d) : "l"(a), "l"(b), "l"(c));
    return d;
}
__device__ __forceinline__ u64 f2dup(float x) {
    u64 d;
    asm("mov.b64 %0, {%1, %2};" : "=l"(d) : "f"(x), "f"(x));
    return d;
}
__device__ __forceinline__ u64 f2pack(float x, float y) {
    u64 d;
    asm("mov.b64 %0, {%1, %2};" : "=l"(d) : "f"(x), "f"(y));
    return d;
}
__device__ __forceinline__ float2 f2unpack(u64 d) {
    float2 r;
    asm("mov.b64 {%0, %1}, %2;" : "=f"(r.x), "=f"(r.y) : "l"(d));
    return r;
}

__global__ __launch_bounds__(512) void k_mlp1(const float* __restrict__ emb,
                                              const float* __restrict__ W,
                                              const float* __restrict__ b) {
    __shared__ float sE[EMBD];
    int bid = blockIdx.x, tid = threadIdx.x;
    if (tid < EMBD) sE[tid] = emb[bid * EMBD + tid];
    __syncthreads();
    float acc = 0.f;
#pragma unroll 16
    for (int k = 0; k < EMBD; k++) acc += sE[k] * __ldg(&W[k * G1D + tid]);
    g_h[bid * G1D + tid] = fmaxf(acc + b[tid], 0.f);
}

// mlp2: x = h @ Wg2 + bg2. Thread owns 8 rows x (cols tx*4..+3 and 64+tx*4..+3):
// B LDS addresses are 16B-strided across the warp -> conflict-free.
__global__ __launch_bounds__(256) void k_mlp2(const float* __restrict__ W,
                                              const float* __restrict__ bias) {
    __shared__ __align__(16) u64 sA[16][128];
    __shared__ __align__(16) float sB[16][128];
    const float* h = g_h;
    int tid = threadIdx.x;
    int n0 = blockIdx.x * 128;
    int tx = tid & 15, ty = tid >> 4;
    int mb = ty * 8;
    int tx4 = tx * 4;
    u64 acc[8][4];
#pragma unroll
    for (int r = 0; r < 8; r++)
#pragma unroll
        for (int c = 0; c < 4; c++) acc[r][c] = 0ull;
    int am = tid >> 1;
    int ak = (tid & 1) * 8;
    int bk = tid >> 4;
    int bn = (tid & 15) * 8;
    for (int k0 = 0; k0 < G1D; k0 += 16) {
        float4 a0 = make_float4(0.f, 0.f, 0.f, 0.f), a1 = a0;
        if (am < NB) {
            const float4* hp = reinterpret_cast<const float4*>(h + am * G1D + k0 + ak);
            a0 = hp[0];
            a1 = hp[1];
        }
        const float4* wp =
            reinterpret_cast<const float4*>(W + (u64)(k0 + bk) * G2D + n0 + bn);
        float4 b0 = wp[0], b1 = wp[1];
        __syncthreads();
        sA[ak + 0][am] = f2dup(a0.x);
        sA[ak + 1][am] = f2dup(a0.y);
        sA[ak + 2][am] = f2dup(a0.z);
        sA[ak + 3][am] = f2dup(a0.w);
        sA[ak + 4][am] = f2dup(a1.x);
        sA[ak + 5][am] = f2dup(a1.y);
        sA[ak + 6][am] = f2dup(a1.z);
        sA[ak + 7][am] = f2dup(a1.w);
        *reinterpret_cast<float4*>(&sB[bk][bn]) = b0;
        *reinterpret_cast<float4*>(&sB[bk][bn + 4]) = b1;
        __syncthreads();
#pragma unroll
        for (int k = 0; k < 16; k++) {
            const ulonglong2* ap = reinterpret_cast<const ulonglong2*>(&sA[k][mb]);
            ulonglong2 av0 = ap[0], av1 = ap[1], av2 = ap[2], av3 = ap[3];
            ulonglong2 bv0 = *reinterpret_cast<const ulonglong2*>(&sB[k][tx4]);
            ulonglong2 bv1 = *reinterpret_cast<const ulonglong2*>(&sB[k][64 + tx4]);
            u64 ar[8] = {av0.x, av0.y, av1.x, av1.y, av2.x, av2.y, av3.x, av3.y};
            u64 br[4] = {bv0.x, bv0.y, bv1.x, bv1.y};
#pragma unroll
            for (int r = 0; r < 8; r++)
#pragma unroll
                for (int c = 0; c < 4; c++) acc[r][c] = f2fma(ar[r], br[c], acc[r][c]);
        }
    }
    float2 bs0 = *reinterpret_cast<const float2*>(bias + n0 + tx4);
    float2 bs1 = *reinterpret_cast<const float2*>(bias + n0 + tx4 + 2);
    float2 bs2 = *reinterpret_cast<const float2*>(bias + n0 + 64 + tx4);
    float2 bs3 = *reinterpret_cast<const float2*>(bias + n0 + 64 + tx4 + 2);
#pragma unroll
    for (int r = 0; r < 8; r++) {
        int row = mb + r;
        if (row < NB) {
            float* op = g_x + (u64)row * G2D + n0;
            float2 v0 = f2unpack(acc[r][0]);
            float2 v1 = f2unpack(acc[r][1]);
            float2 v2 = f2unpack(acc[r][2]);
            float2 v3 = f2unpack(acc[r][3]);
            *reinterpret_cast<float4*>(op + tx4) =
                make_float4(v0.x + bs0.x, v0.y + bs0.y, v1.x + bs1.x, v1.y + bs1.y);
            *reinterpret_cast<float4*>(op + 64 + tx4) =
                make_float4(v2.x + bs2.x, v2.y + bs2.y, v3.x + bs3.x, v3.y + bs3.y);
        }
    }
}

__global__ void k_zero_cnt() {
    int i = blockIdx.x * 256 + threadIdx.x;
    if (i < NN) g_cnt[i] = 0;
}
__global__ void k_hist(const int* __restrict__ ei) {
    int e = blockIdx.x * 256 + threadIdx.x;
    if (e < NE) atomicAdd(&g_cnt[__ldg(&ei[NE + e])], 1);
}
__global__ __launch_bounds__(512) void k_scan1() {
    __shared__ int s[512];
    int i = blockIdx.x * 512 + threadIdx.x;
    int v = (i < NN) ? g_cnt[i] : 0;
    s[threadIdx.x] = v;
    __syncthreads();
#pragma unroll
    for (int off = 1; off < 512; off <<= 1) {
        int t = (threadIdx.x >= off) ? s[threadIdx.x - off] : 0;
        __syncthreads();
        s[threadIdx.x] += t;
        __syncthreads();
    }
    if (i < NN) g_rowptr[i] = s[threadIdx.x] - v;
    if (threadIdx.x == 511) g_bsum[blockIdx.x] = s[511];
}
__global__ __launch_bounds__(256) void k_scan2() {
    __shared__ int s[256];
    int tid = threadIdx.x;
    int v = (tid < NSCAN_BLKS) ? g_bsum[tid] : 0;
    s[tid] = v;
    __syncthreads();
#pragma unroll
    for (int off = 1; off < 256; off <<= 1) {
        int t = (tid >= off) ? s[tid - off] : 0;
        __syncthreads();
        s[tid] += t;
        __syncthreads();
    }
    if (tid < NSCAN_BLKS) g_bsum[tid] = s[tid] - v;
}
__global__ void k_scan3() {
    int i = blockIdx.x * 256 + threadIdx.x;
    if (i < NN) {
        int r = g_rowptr[i] + g_bsum[i >> 9];
        g_rowptr[i] = r;
        g_ofs[i] = r;
    }
    if (i == 0) g_rowptr[NN] = NE;
}
__global__ void k_permute(const int* __restrict__ ei) {
    int e = blockIdx.x * 256 + threadIdx.x;
    if (e < NE) {
        int dst = __ldg(&ei[NE + e]);
        int pos = atomicAdd(&g_ofs[dst], 1);
        g_perm[pos] = e;
    }
}
__global__ __launch_bounds__(256) void k_gatherperm(const int* __restrict__ ei,
                                                    const float* __restrict__ ea) {
    int tid = threadIdx.x;
    int t = tid & 3;
    int pos = blockIdx.x * 64 + (tid >> 2);
    int eo = __ldg(&g_perm[pos]);
    if (t == 0) g_srcp[pos] = __ldg(&ei[eo]);
    float4 v = __ldg(reinterpret_cast<const float4*>(ea) + (u64)eo * 4 + t);
    reinterpret_cast<float4*>(g_eap)[(u64)pos * 4 + t] = v;
}

__global__ __launch_bounds__(128) void k_ynode(const float* __restrict__ x,
                                               const float* __restrict__ mW,
                                               const float* __restrict__ mb) {
    __shared__ float sX[64][65];
    __shared__ float sW[64][64];
    int tid = threadIdx.x;
    int node0 = blockIdx.x * 64;
    for (int i = tid; i < 64 * 64; i += 128) sW[i >> 6][i & 63] = mW[i];
    for (int i = tid; i < 64 * 64; i += 128) {
        int n = i >> 6, c = i & 63;
        int nn = node0 + n;
        if (nn >= NN) nn = NN - 1;
        sX[n][c] = x[(u64)nn * DD + c];
    }
    __syncthreads();
    int f0 = (tid & 7) * 8;
    int n0 = (tid >> 3) * 4;
    u64 acc[4][4];
#pragma unroll
    for (int j = 0; j < 4; j++)
#pragma unroll
        for (int c = 0; c < 4; c++) acc[j][c] = 0ull;
#pragma unroll 8
    for (int k = 0; k < 64; k++) {
        ulonglong2 w01 = *reinterpret_cast<const ulonglong2*>(&sW[k][f0]);
        ulonglong2 w23 = *reinterpret_cast<const ulonglong2*>(&sW[k][f0 + 4]);
#pragma unroll
        for (int j = 0; j < 4; j++) {
            u64 a = f2dup(sX[n0 + j][k]);
            acc[j][0] = f2fma(a, w01.x, acc[j][0]);
            acc[j][1] = f2fma(a, w01.y, acc[j][1]);
            acc[j][2] = f2fma(a, w23.x, acc[j][2]);
            acc[j][3] = f2fma(a, w23.y, acc[j][3]);
        }
    }
    float2 bv[4];
#pragma unroll
    for (int c = 0; c < 4; c++)
        bv[c] = *reinterpret_cast<const float2*>(mb + f0 + 2 * c);
#pragma unroll
    for (int j = 0; j < 4; j++) {
        int nn = node0 + n0 + j;
        if (nn < NN) {
            float o[8];
#pragma unroll
            for (int c = 0; c < 4; c++) {
                float2 v = f2unpack(acc[j][c]);
                o[2 * c] = v.x + bv[c].x;
                o[2 * c + 1] = v.y + bv[c].y;
            }
            float* yp = g_y + (u64)nn * DD + f0;
            *reinterpret_cast<float4*>(yp) = make_float4(o[0], o[1], o[2], o[3]);
            *reinterpret_cast<float4*>(yp + 4) = make_float4(o[4], o[5], o[6], o[7]);
        }
    }
}

// k_agg: round-5 2-edge unrolled version (best measured)
__global__ __launch_bounds__(256) void k_agg(const float* __restrict__ mW) {
    __shared__ float2 sWe[16][32];
    int tid = threadIdx.x;
    for (int i = tid; i < 512; i += 256) {
        int k = i >> 5, l = i & 31;
        sWe[k][l] = *reinterpret_cast<const float2*>(mW + (64 + k) * DD + 2 * l);
    }
    __syncthreads();
    int lane = tid & 31;
    int node = blockIdx.x * 8 + (tid >> 5);
    u64 w[16];
#pragma unroll
    for (int k = 0; k < 16; k++) {
        float2 t = sWe[k][lane];
        w[k] = f2pack(t.x, t.y);
    }
    int e = g_rowptr[node], e_end = g_rowptr[node + 1];
    float accx = 0.f, accy = 0.f;
    for (; e + 2 <= e_end; e += 2) {
        int s0 = __ldg(&g_srcp[e]);
        int s1 = __ldg(&g_srcp[e + 1]);
        const float4* p = reinterpret_cast<const float4*>(g_eap + (u64)e * ECD);
        float4 a0 = __ldg(p + 0), a1 = __ldg(p + 1), a2 = __ldg(p + 2), a3 = __ldg(p + 3);
        float4 c0 = __ldg(p + 4), c1 = __ldg(p + 5), c2 = __ldg(p + 6), c3 = __ldg(p + 7);
        float2 y0 = __ldg(reinterpret_cast<const float2*>(g_y + (u64)s0 * DD) + lane);
        float2 y1 = __ldg(reinterpret_cast<const float2*>(g_y + (u64)s1 * DD) + lane);
        {
            u64 z0 = 0ull, z1 = 0ull;
            z0 = f2fma(f2dup(a0.x), w[0], z0);  z1 = f2fma(f2dup(a0.y), w[1], z1);
            z0 = f2fma(f2dup(a0.z), w[2], z0);  z1 = f2fma(f2dup(a0.w), w[3], z1);
            z0 = f2fma(f2dup(a1.x), w[4], z0);  z1 = f2fma(f2dup(a1.y), w[5], z1);
            z0 = f2fma(f2dup(a1.z), w[6], z0);  z1 = f2fma(f2dup(a1.w), w[7], z1);
            z0 = f2fma(f2dup(a2.x), w[8], z0);  z1 = f2fma(f2dup(a2.y), w[9], z1);
            z0 = f2fma(f2dup(a2.z), w[10], z0); z1 = f2fma(f2dup(a2.w), w[11], z1);
            z0 = f2fma(f2dup(a3.x), w[12], z0); z1 = f2fma(f2dup(a3.y), w[13], z1);
            z0 = f2fma(f2dup(a3.z), w[14], z0); z1 = f2fma(f2dup(a3.w), w[15], z1);
            float2 za = f2unpack(z0), zb = f2unpack(z1);
            accx += fmaxf(y0.x + za.x + zb.x, 0.f);
            accy += fmaxf(y0.y + za.y + zb.y, 0.f);
        }
        {
            u64 z0 = 0ull, z1 = 0ull;
            z0 = f2fma(f2dup(c0.x), w[0], z0);  z1 = f2fma(f2dup(c0.y), w[1], z1);
            z0 = f2fma(f2dup(c0.z), w[2], z0);  z1 = f2fma(f2dup(c0.w), w[3], z1);
            z0 = f2fma(f2dup(c1.x), w[4], z0);  z1 = f2fma(f2dup(c1.y), w[5], z1);
            z0 = f2fma(f2dup(c1.z), w[6], z0);  z1 = f2fma(f2dup(c1.w), w[7], z1);
            z0 = f2fma(f2dup(c2.x), w[8], z0);  z1 = f2fma(f2dup(c2.y), w[9], z1);
            z0 = f2fma(f2dup(c2.z), w[10], z0); z1 = f2fma(f2dup(c2.w), w[11], z1);
            z0 = f2fma(f2dup(c3.x), w[12], z0); z1 = f2fma(f2dup(c3.y), w[13], z1);
            z0 = f2fma(f2dup(c3.z), w[14], z0); z1 = f2fma(f2dup(c3.w), w[15], z1);
            float2 za = f2unpack(z0), zb = f2unpack(z1);
            accx += fmaxf(y1.x + za.x + zb.x, 0.f);
            accy += fmaxf(y1.y + za.y + zb.y, 0.f);
        }
    }
    if (e < e_end) {
        int s0 = __ldg(&g_srcp[e]);
        const float4* p = reinterpret_cast<const float4*>(g_eap + (u64)e * ECD);
        float4 a0 = __ldg(p + 0), a1 = __ldg(p + 1), a2 = __ldg(p + 2), a3 = __ldg(p + 3);
        float2 y0 = __ldg(reinterpret_cast<const float2*>(g_y + (u64)s0 * DD) + lane);
        u64 z0 = 0ull, z1 = 0ull;
        z0 = f2fma(f2dup(a0.x), w[0], z0);  z1 = f2fma(f2dup(a0.y), w[1], z1);
        z0 = f2fma(f2dup(a0.z), w[2], z0);  z1 = f2fma(f2dup(a0.w), w[3], z1);
        z0 = f2fma(f2dup(a1.x), w[4], z0);  z1 = f2fma(f2dup(a1.y), w[5], z1);
        z0 = f2fma(f2dup(a1.z), w[6], z0);  z1 = f2fma(f2dup(a1.w), w[7], z1);
        z0 = f2fma(f2dup(a2.x), w[8], z0);  z1 = f2fma(f2dup(a2.y), w[9], z1);
        z0 = f2fma(f2dup(a2.z), w[10], z0); z1 = f2fma(f2dup(a2.w), w[11], z1);
        z0 = f2fma(f2dup(a3.x), w[12], z0); z1 = f2fma(f2dup(a3.y), w[13], z1);
        z0 = f2fma(f2dup(a3.z), w[14], z0); z1 = f2fma(f2dup(a3.w), w[15], z1);
        float2 za = f2unpack(z0), zb = f2unpack(z1);
        accx += fmaxf(y0.x + za.x + zb.x, 0.f);
        accy += fmaxf(y0.y + za.y + zb.y, 0.f);
    }
    *reinterpret_cast<float2*>(g_agg + (u64)node * DD + 2 * lane) =
        make_float2(accx, accy);
}

#define UPD_SMEM (128 * 130 * 4 + 128 * 64 * 4)
__global__ __launch_bounds__(256) void k_update(const float* __restrict__ x,
                                                const float* __restrict__ uW,
                                                const float* __restrict__ ub,
                                                float* __restrict__ xo) {
    extern __shared__ float us[];
    float(*sIn)[130] = reinterpret_cast<float(*)[130]>(us);
    float(*sW)[64] = reinterpret_cast<float(*)[64]>(us + 128 * 130);
    int tid = threadIdx.x;
    int node0 = blockIdx.x * 128;
    for (int i = tid; i < 128 * 64; i += 256) sW[i >> 6][i & 63] = uW[i];
    for (int i = tid; i < 128 * 128; i += 256) {
        int n = i >> 7, c = i & 127;
        int nn = node0 + n;
        if (nn >= NN) nn = NN - 1;
        float v = (c < 64) ? x[(u64)nn * DD + c] : g_agg[(u64)nn * DD + c - 64];
        sIn[n][c] = v;
    }
    __syncthreads();
    int f0 = (tid & 7) * 8;
    int n0 = (tid >> 3) * 4;
    u64 acc[4][4];
#pragma unroll
    for (int j = 0; j < 4; j++)
#pragma unroll
        for (int c = 0; c < 4; c++) acc[j][c] = 0ull;
#pragma unroll 8
    for (int k = 0; k < 128; k++) {
        ulonglong2 w01 = *reinterpret_cast<const ulonglong2*>(&sW[k][f0]);
        ulonglong2 w23 = *reinterpret_cast<const ulonglong2*>(&sW[k][f0 + 4]);
#pragma unroll
        for (int j = 0; j < 4; j++) {
            u64 a = f2dup(sIn[n0 + j][k]);
            acc[j][0] = f2fma(a, w01.x, acc[j][0]);
            acc[j][1] = f2fma(a, w01.y, acc[j][1]);
            acc[j][2] = f2fma(a, w23.x, acc[j][2]);
            acc[j][3] = f2fma(a, w23.y, acc[j][3]);
        }
    }
    float2 bv[4];
#pragma unroll
    for (int c = 0; c < 4; c++)
        bv[c] = *reinterpret_cast<const float2*>(ub + f0 + 2 * c);
#pragma unroll
    for (int j = 0; j < 4; j++) {
        int nn = node0 + n0 + j;
        if (nn < NN) {
            float o[8];
#pragma unroll
            for (int c = 0; c < 4; c++) {
                float2 v = f2unpack(acc[j][c]);
                o[2 * c] = fmaxf(v.x + bv[c].x, 0.f);
                o[2 * c + 1] = fmaxf(v.y + bv[c].y, 0.f);
            }
            float* op = xo + (u64)nn * DD + f0;
            *reinterpret_cast<float4*>(op) = make_float4(o[0], o[1], o[2], o[3]);
            *reinterpret_cast<float4*>(op + 4) = make_float4(o[4], o[5], o[6], o[7]);
        }
    }
}

#define NM_SMEM (64 * 128 * 4 + 64 * 65 * 4 + 64 * 130 * 4 + 128 * 4 * 4)
__global__ __launch_bounds__(256) void k_nodemlp(const float* __restrict__ W1,
                                                 const float* __restrict__ b1,
                                                 const float* __restrict__ W2,
                                                 const float* __restrict__ b2,
                                                 float* __restrict__ out) {
    extern __shared__ float nsm[];
    float(*sW1)[128] = reinterpret_cast<float(*)[128]>(nsm);
    float(*sX)[65] = reinterpret_cast<float(*)[65]>(nsm + 64 * 128);
    float(*sH)[130] = reinterpret_cast<float(*)[130]>(nsm + 64 * 128 + 64 * 65);
    float(*sW2)[4] =
        reinterpret_cast<float(*)[4]>(nsm + 64 * 128 + 64 * 65 + 64 * 130);
    int tid = threadIdx.x;
    int node0 = blockIdx.x * 64;
    for (int i = tid; i < 64 * 128; i += 256) sW1[i >> 7][i & 127] = W1[i];
    if (tid < 128) {
        sW2[tid][0] = W2[tid * 3 + 0];
        sW2[tid][1] = W2[tid * 3 + 1];
        sW2[tid][2] = W2[tid * 3 + 2];
    }
    for (int i = tid; i < 64 * 64; i += 256) {
        int n = i >> 6, c = i & 63;
        int nn = node0 + n;
        if (nn >= NN) nn = NN - 1;
        sX[n][c] = g_x[(u64)nn * DD + c];
    }
    __syncthreads();
    int f0 = (tid & 15) * 8;
    int n0 = (tid >> 4) * 4;
    u64 acc[4][4];
#pragma unroll
    for (int j = 0; j < 4; j++)
#pragma unroll
        for (int c = 0; c < 4; c++) acc[j][c] = 0ull;
#pragma unroll 8
    for (int k = 0; k < 64; k++) {
        ulonglong2 w01 = *reinterpret_cast<const ulonglong2*>(&sW1[k][f0]);
        ulonglong2 w23 = *reinterpret_cast<const ulonglong2*>(&sW1[k][f0 + 4]);
#pragma unroll
        for (int j = 0; j < 4; j++) {
            u64 a = f2dup(sX[n0 + j][k]);
            acc[j][0] = f2fma(a, w01.x, acc[j][0]);
            acc[j][1] = f2fma(a, w01.y, acc[j][1]);
            acc[j][2] = f2fma(a, w23.x, acc[j][2]);
            acc[j][3] = f2fma(a, w23.y, acc[j][3]);
        }
    }
    float2 bv[4];
#pragma unroll
    for (int c = 0; c < 4; c++)
        bv[c] = *reinterpret_cast<const float2*>(b1 + f0 + 2 * c);
#pragma unroll
    for (int j = 0; j < 4; j++) {
#pragma unroll
        for (int c = 0; c < 4; c++) {
            float2 v = f2unpack(acc[j][c]);
            sH[n0 + j][f0 + 2 * c] = fmaxf(v.x + bv[c].x, 0.f);
            sH[n0 + j][f0 + 2 * c + 1] = fmaxf(v.y + bv[c].y, 0.f);
        }
    }
    __syncthreads();
    if (tid < 192) {
        int node = tid / 3, c = tid % 3;
        int nn = node0 + node;
        if (nn < NN) {
            float o = b2[c];
#pragma unroll 16
            for (int j = 0; j < 128; j++) o += sH[node][j] * sW2[j][c];
            out[(u64)nn * 3 + c] = o;
        }
    }
}

extern "C" void kernel_launch(void* const* d_in, const int* in_sizes, int n_in,
                              void* d_out, int out_size) {
    const float* emb = (const float*)d_in[0];
    const int* edge_index = (const int*)d_in[1];
    const float* edge_attr = (const float*)d_in[2];
    const float* Wg1 = (const float*)d_in[3];
    const float* bg1 = (const float*)d_in[4];
    const float* Wg2 = (const float*)d_in[5];
    const float* bg2 = (const float*)d_in[6];
    const float* mW0 = (const float*)d_in[7];
    const float* mb0 = (const float*)d_in[8];
    const float* uW0 = (const float*)d_in[9];
    const float* ub0 = (const float*)d_in[10];
    const float* mW1 = (const float*)d_in[11];
    const float* mb1 = (const float*)d_in[12];
    const float* uW1 = (const float*)d_in[13];
    const float* ub1 = (const float*)d_in[14];
    const float* nW1 = (const float*)d_in[15];
    const float* nb1 = (const float*)d_in[16];
    const float* nW2 = (const float*)d_in[17];
    const float* nb2 = (const float*)d_in[18];
    float* out = (float*)d_out;

    float *p_x, *p_x2;
    cudaGetSymbolAddress((void**)&p_x, g_x);
    cudaGetSymbolAddress((void**)&p_x2, g_x2);

    cudaFuncSetAttribute(k_update, cudaFuncAttributeMaxDynamicSharedMemorySize,
                         UPD_SMEM);
    cudaFuncSetAttribute(k_nodemlp, cudaFuncAttributeMaxDynamicSharedMemorySize,
                         NM_SMEM);

    // launch order arranged so the profiled launch (#3) is k_mlp2
    k_zero_cnt<<<(NN + 255) / 256, 256>>>();
    k_hist<<<(NE + 255) / 256, 256>>>(edge_index);
    k_mlp1<<<NB, 512>>>(emb, Wg1, bg1);
    k_mlp2<<<G2D / 128, 256>>>(Wg2, bg2);
    k_scan1<<<NSCAN_BLKS, 512>>>();
    k_scan2<<<1, 256>>>();
    k_scan3<<<(NN + 255) / 256, 256>>>();
    k_permute<<<(NE + 255) / 256, 256>>>(edge_index);
    k_gatherperm<<<NE / 64, 256>>>(edge_index, edge_attr);

    k_ynode<<<(NN + 63) / 64, 128>>>(p_x, mW0, mb0);
    k_agg<<<NN / 8, 256>>>(mW0);
    k_update<<<(NN + 127) / 128, 256, UPD_SMEM>>>(p_x, uW0, ub0, p_x2);
    k_ynode<<<(NN + 63) / 64, 128>>>(p_x2, mW1, mb1);
    k_agg<<<NN / 8, 256>>>(mW1);
    k_update<<<(NN + 127) / 128, 256, UPD_SMEM>>>(p_x2, uW1, ub1, p_x);
    k_nodemlp<<<(NN + 63) / 64, 256, NM_SMEM>>>(nW1, nb1, nW2, nb2, out);
}

// round 8
// speedup vs baseline: 1.1293x; 1.0287x over previous
#include <cuda_runtime.h>

typedef unsigned long long u64;

#define NN 100000
#define NE 1600000
#define EMBD 128
#define G1D 512
#define G2D 64000
#define DD 64
#define ECD 16
#define NB 100
#define NSCAN_BLKS 196

__device__ float g_h[NB * G1D];
__device__ float g_x[NN * DD];
__device__ float g_x2[NN * DD];
__device__ float g_y[NN * DD];
__device__ float g_agg[NN * DD];
__device__ int g_cnt[NN];
__device__ int g_rowptr[NN + 1];
__device__ int g_ofs[NN];
__device__ int g_bsum[NSCAN_BLKS];
__device__ int g_srcp[NE];
__device__ float g_eap[(u64)NE * ECD];

__device__ __forceinline__ u64 f2fma(u64 a, u64 b, u64 c) {
    u64 d;
    asm("fma.rn.f32x2 %0, %1, %2, %3;" : "=l"(d) : "l"(a), "l"(b), "l"(c));
    return d;
}
__device__ __forceinline__ u64 f2dup(float x) {
    u64 d;
    asm("mov.b64 %0, {%1, %2};" : "=l"(d) : "f"(x), "f"(x));
    return d;
}
__device__ __forceinline__ u64 f2pack(float x, float y) {
    u64 d;
    asm("mov.b64 %0, {%1, %2};" : "=l"(d) : "f"(x), "f"(y));
    return d;
}
__device__ __forceinline__ float2 f2unpack(u64 d) {
    float2 r;
    asm("mov.b64 {%0, %1}, %2;" : "=f"(r.x), "=f"(r.y) : "l"(d));
    return r;
}

__global__ __launch_bounds__(512) void k_mlp1(const float* __restrict__ emb,
                                              const float* __restrict__ W,
                                              const float* __restrict__ b) {
    __shared__ float sE[EMBD];
    int bid = blockIdx.x, tid = threadIdx.x;
    if (tid < EMBD) sE[tid] = emb[bid * EMBD + tid];
    __syncthreads();
    float acc = 0.f;
#pragma unroll 16
    for (int k = 0; k < EMBD; k++) acc += sE[k] * __ldg(&W[k * G1D + tid]);
    g_h[bid * G1D + tid] = fmaxf(acc + b[tid], 0.f);
}

// mlp2: x = h @ Wg2 + bg2. A stored as float (2 LDS.128/k), B conflict-free
// (two 4-col groups), next-tile W prefetched into regs before compute.
__global__ __launch_bounds__(256) void k_mlp2(const float* __restrict__ W,
                                              const float* __restrict__ bias) {
    __shared__ __align__(16) float sA[16][128];
    __shared__ __align__(16) float sB[16][128];
    const float* h = g_h;
    int tid = threadIdx.x;
    int n0 = blockIdx.x * 128;
    int tx = tid & 15, ty = tid >> 4;
    int mb = ty * 8;
    int tx4 = tx * 4;
    u64 acc[8][4];
#pragma unroll
    for (int r = 0; r < 8; r++)
#pragma unroll
        for (int c = 0; c < 4; c++) acc[r][c] = 0ull;
    int am = tid >> 1;
    int ak = (tid & 1) * 8;
    int bk = tid >> 4;
    int bn = (tid & 15) * 8;

    float4 a0 = make_float4(0.f, 0.f, 0.f, 0.f), a1 = a0;
    if (am < NB) {
        const float4* hp = reinterpret_cast<const float4*>(h + am * G1D + ak);
        a0 = hp[0];
        a1 = hp[1];
    }
    const float4* wp0 = reinterpret_cast<const float4*>(W + (u64)bk * G2D + n0 + bn);
    float4 b0 = wp0[0], b1 = wp0[1];

    for (int k0 = 0; k0 < G1D; k0 += 16) {
        __syncthreads();
        sA[ak + 0][am] = a0.x;
        sA[ak + 1][am] = a0.y;
        sA[ak + 2][am] = a0.z;
        sA[ak + 3][am] = a0.w;
        sA[ak + 4][am] = a1.x;
        sA[ak + 5][am] = a1.y;
        sA[ak + 6][am] = a1.z;
        sA[ak + 7][am] = a1.w;
        *reinterpret_cast<float4*>(&sB[bk][bn]) = b0;
        *reinterpret_cast<float4*>(&sB[bk][bn + 4]) = b1;
        __syncthreads();
        int k1 = k0 + 16;
        if (k1 < G1D) {
            if (am < NB) {
                const float4* hp =
                    reinterpret_cast<const float4*>(h + am * G1D + k1 + ak);
                a0 = hp[0];
                a1 = hp[1];
            }
            const float4* wp =
                reinterpret_cast<const float4*>(W + (u64)(k1 + bk) * G2D + n0 + bn);
            b0 = wp[0];
            b1 = wp[1];
        }
#pragma unroll
        for (int k = 0; k < 16; k++) {
            const float4* ap = reinterpret_cast<const float4*>(&sA[k][mb]);
            float4 af0 = ap[0], af1 = ap[1];
            ulonglong2 bv0 = *reinterpret_cast<const ulonglong2*>(&sB[k][tx4]);
            ulonglong2 bv1 = *reinterpret_cast<const ulonglong2*>(&sB[k][64 + tx4]);
            u64 ar[8] = {f2dup(af0.x), f2dup(af0.y), f2dup(af0.z), f2dup(af0.w),
                         f2dup(af1.x), f2dup(af1.y), f2dup(af1.z), f2dup(af1.w)};
            u64 br[4] = {bv0.x, bv0.y, bv1.x, bv1.y};
#pragma unroll
            for (int r = 0; r < 8; r++)
#pragma unroll
                for (int c = 0; c < 4; c++) acc[r][c] = f2fma(ar[r], br[c], acc[r][c]);
        }
    }
    float2 bs0 = *reinterpret_cast<const float2*>(bias + n0 + tx4);
    float2 bs1 = *reinterpret_cast<const float2*>(bias + n0 + tx4 + 2);
    float2 bs2 = *reinterpret_cast<const float2*>(bias + n0 + 64 + tx4);
    float2 bs3 = *reinterpret_cast<const float2*>(bias + n0 + 64 + tx4 + 2);
#pragma unroll
    for (int r = 0; r < 8; r++) {
        int row = mb + r;
        if (row < NB) {
            float* op = g_x + (u64)row * G2D + n0;
            float2 v0 = f2unpack(acc[r][0]);
            float2 v1 = f2unpack(acc[r][1]);
            float2 v2 = f2unpack(acc[r][2]);
            float2 v3 = f2unpack(acc[r][3]);
            *reinterpret_cast<float4*>(op + tx4) =
                make_float4(v0.x + bs0.x, v0.y + bs0.y, v1.x + bs1.x, v1.y + bs1.y);
            *reinterpret_cast<float4*>(op + 64 + tx4) =
                make_float4(v2.x + bs2.x, v2.y + bs2.y, v3.x + bs3.x, v3.y + bs3.y);
        }
    }
}

__global__ void k_zero_cnt() {
    int i = blockIdx.x * 256 + threadIdx.x;
    if (i < NN) g_cnt[i] = 0;
}
__global__ void k_hist(const int* __restrict__ ei) {
    int e = blockIdx.x * 256 + threadIdx.x;
    if (e < NE) atomicAdd(&g_cnt[__ldg(&ei[NE + e])], 1);
}
__global__ __launch_bounds__(512) void k_scan1() {
    __shared__ int s[512];
    int i = blockIdx.x * 512 + threadIdx.x;
    int v = (i < NN) ? g_cnt[i] : 0;
    s[threadIdx.x] = v;
    __syncthreads();
#pragma unroll
    for (int off = 1; off < 512; off <<= 1) {
        int t = (threadIdx.x >= off) ? s[threadIdx.x - off] : 0;
        __syncthreads();
        s[threadIdx.x] += t;
        __syncthreads();
    }
    if (i < NN) g_rowptr[i] = s[threadIdx.x] - v;
    if (threadIdx.x == 511) g_bsum[blockIdx.x] = s[511];
}
__global__ __launch_bounds__(256) void k_scan2() {
    __shared__ int s[256];
    int tid = threadIdx.x;
    int v = (tid < NSCAN_BLKS) ? g_bsum[tid] : 0;
    s[tid] = v;
    __syncthreads();
#pragma unroll
    for (int off = 1; off < 256; off <<= 1) {
        int t = (tid >= off) ? s[tid - off] : 0;
        __syncthreads();
        s[tid] += t;
        __syncthreads();
    }
    if (tid < NSCAN_BLKS) g_bsum[tid] = s[tid] - v;
}
__global__ void k_scan3() {
    int i = blockIdx.x * 256 + threadIdx.x;
    if (i < NN) {
        int r = g_rowptr[i] + g_bsum[i >> 9];
        g_rowptr[i] = r;
        g_ofs[i] = r;
    }
    if (i == 0) g_rowptr[NN] = NE;
}

// fused permute + gather: scatter src and edge_attr directly into dst-sorted order
__global__ __launch_bounds__(256) void k_permgather(const int* __restrict__ ei,
                                                    const float* __restrict__ ea) {
    int e = blockIdx.x * 256 + threadIdx.x;
    if (e < NE) {
        int dst = __ldg(&ei[NE + e]);
        int src = __ldg(&ei[e]);
        int pos = atomicAdd(&g_ofs[dst], 1);
        g_srcp[pos] = src;
        const float4* src4 = reinterpret_cast<const float4*>(ea + (u64)e * ECD);
        float4 v0 = __ldg(src4 + 0);
        float4 v1 = __ldg(src4 + 1);
        float4 v2 = __ldg(src4 + 2);
        float4 v3 = __ldg(src4 + 3);
        float4* dst4 = reinterpret_cast<float4*>(g_eap + (u64)pos * ECD);
        dst4[0] = v0;
        dst4[1] = v1;
        dst4[2] = v2;
        dst4[3] = v3;
    }
}

__global__ __launch_bounds__(128) void k_ynode(const float* __restrict__ x,
                                               const float* __restrict__ mW,
                                               const float* __restrict__ mb) {
    __shared__ float sX[64][65];
    __shared__ float sW[64][64];
    int tid = threadIdx.x;
    int node0 = blockIdx.x * 64;
    for (int i = tid; i < 64 * 64; i += 128) sW[i >> 6][i & 63] = mW[i];
    for (int i = tid; i < 64 * 64; i += 128) {
        int n = i >> 6, c = i & 63;
        int nn = node0 + n;
        if (nn >= NN) nn = NN - 1;
        sX[n][c] = x[(u64)nn * DD + c];
    }
    __syncthreads();
    int f0 = (tid & 7) * 8;
    int n0 = (tid >> 3) * 4;
    u64 acc[4][4];
#pragma unroll
    for (int j = 0; j < 4; j++)
#pragma unroll
        for (int c = 0; c < 4; c++) acc[j][c] = 0ull;
#pragma unroll 8
    for (int k = 0; k < 64; k++) {
        ulonglong2 w01 = *reinterpret_cast<const ulonglong2*>(&sW[k][f0]);
        ulonglong2 w23 = *reinterpret_cast<const ulonglong2*>(&sW[k][f0 + 4]);
#pragma unroll
        for (int j = 0; j < 4; j++) {
            u64 a = f2dup(sX[n0 + j][k]);
            acc[j][0] = f2fma(a, w01.x, acc[j][0]);
            acc[j][1] = f2fma(a, w01.y, acc[j][1]);
            acc[j][2] = f2fma(a, w23.x, acc[j][2]);
            acc[j][3] = f2fma(a, w23.y, acc[j][3]);
        }
    }
    float2 bv[4];
#pragma unroll
    for (int c = 0; c < 4; c++)
        bv[c] = *reinterpret_cast<const float2*>(mb + f0 + 2 * c);
#pragma unroll
    for (int j = 0; j < 4; j++) {
        int nn = node0 + n0 + j;
        if (nn < NN) {
            float o[8];
#pragma unroll
            for (int c = 0; c < 4; c++) {
                float2 v = f2unpack(acc[j][c]);
                o[2 * c] = v.x + bv[c].x;
                o[2 * c + 1] = v.y + bv[c].y;
            }
            float* yp = g_y + (u64)nn * DD + f0;
            *reinterpret_cast<float4*>(yp) = make_float4(o[0], o[1], o[2], o[3]);
            *reinterpret_cast<float4*>(yp + 4) = make_float4(o[4], o[5], o[6], o[7]);
        }
    }
}

// k_agg: 2-edge unrolled (best measured variant)
__global__ __launch_bounds__(256) void k_agg(const float* __restrict__ mW) {
    __shared__ float2 sWe[16][32];
    int tid = threadIdx.x;
    for (int i = tid; i < 512; i += 256) {
        int k = i >> 5, l = i & 31;
        sWe[k][l] = *reinterpret_cast<const float2*>(mW + (64 + k) * DD + 2 * l);
    }
    __syncthreads();
    int lane = tid & 31;
    int node = blockIdx.x * 8 + (tid >> 5);
    u64 w[16];
#pragma unroll
    for (int k = 0; k < 16; k++) {
        float2 t = sWe[k][lane];
        w[k] = f2pack(t.x, t.y);
    }
    int e = g_rowptr[node], e_end = g_rowptr[node + 1];
    float accx = 0.f, accy = 0.f;
    for (; e + 2 <= e_end; e += 2) {
        int s0 = __ldg(&g_srcp[e]);
        int s1 = __ldg(&g_srcp[e + 1]);
        const float4* p = reinterpret_cast<const float4*>(g_eap + (u64)e * ECD);
        float4 a0 = __ldg(p + 0), a1 = __ldg(p + 1), a2 = __ldg(p + 2), a3 = __ldg(p + 3);
        float4 c0 = __ldg(p + 4), c1 = __ldg(p + 5), c2 = __ldg(p + 6), c3 = __ldg(p + 7);
        float2 y0 = __ldg(reinterpret_cast<const float2*>(g_y + (u64)s0 * DD) + lane);
        float2 y1 = __ldg(reinterpret_cast<const float2*>(g_y + (u64)s1 * DD) + lane);
        {
            u64 z0 = 0ull, z1 = 0ull;
            z0 = f2fma(f2dup(a0.x), w[0], z0);  z1 = f2fma(f2dup(a0.y), w[1], z1);
            z0 = f2fma(f2dup(a0.z), w[2], z0);  z1 = f2fma(f2dup(a0.w), w[3], z1);
            z0 = f2fma(f2dup(a1.x), w[4], z0);  z1 = f2fma(f2dup(a1.y), w[5], z1);
            z0 = f2fma(f2dup(a1.z), w[6], z0);  z1 = f2fma(f2dup(a1.w), w[7], z1);
            z0 = f2fma(f2dup(a2.x), w[8], z0);  z1 = f2fma(f2dup(a2.y), w[9], z1);
            z0 = f2fma(f2dup(a2.z), w[10], z0); z1 = f2fma(f2dup(a2.w), w[11], z1);
            z0 = f2fma(f2dup(a3.x), w[12], z0); z1 = f2fma(f2dup(a3.y), w[13], z1);
            z0 = f2fma(f2dup(a3.z), w[14], z0); z1 = f2fma(f2dup(a3.w), w[15], z1);
            float2 za = f2unpack(z0), zb = f2unpack(z1);
            accx += fmaxf(y0.x + za.x + zb.x, 0.f);
            accy += fmaxf(y0.y + za.y + zb.y, 0.f);
        }
        {
            u64 z0 = 0ull, z1 = 0ull;
            z0 = f2fma(f2dup(c0.x), w[0], z0);  z1 = f2fma(f2dup(c0.y), w[1], z1);
            z0 = f2fma(f2dup(c0.z), w[2], z0);  z1 = f2fma(f2dup(c0.w), w[3], z1);
            z0 = f2fma(f2dup(c1.x), w[4], z0);  z1 = f2fma(f2dup(c1.y), w[5], z1);
            z0 = f2fma(f2dup(c1.z), w[6], z0);  z1 = f2fma(f2dup(c1.w), w[7], z1);
            z0 = f2fma(f2dup(c2.x), w[8], z0);  z1 = f2fma(f2dup(c2.y), w[9], z1);
            z0 = f2fma(f2dup(c2.z), w[10], z0); z1 = f2fma(f2dup(c2.w), w[11], z1);
            z0 = f2fma(f2dup(c3.x), w[12], z0); z1 = f2fma(f2dup(c3.y), w[13], z1);
            z0 = f2fma(f2dup(c3.z), w[14], z0); z1 = f2fma(f2dup(c3.w), w[15], z1);
            float2 za = f2unpack(z0), zb = f2unpack(z1);
            accx += fmaxf(y1.x + za.x + zb.x, 0.f);
            accy += fmaxf(y1.y + za.y + zb.y, 0.f);
        }
    }
    if (e < e_end) {
        int s0 = __ldg(&g_srcp[e]);
        const float4* p = reinterpret_cast<const float4*>(g_eap + (u64)e * ECD);
        float4 a0 = __ldg(p + 0), a1 = __ldg(p + 1), a2 = __ldg(p + 2), a3 = __ldg(p + 3);
        float2 y0 = __ldg(reinterpret_cast<const float2*>(g_y + (u64)s0 * DD) + lane);
        u64 z0 = 0ull, z1 = 0ull;
        z0 = f2fma(f2dup(a0.x), w[0], z0);  z1 = f2fma(f2dup(a0.y), w[1], z1);
        z0 = f2fma(f2dup(a0.z), w[2], z0);  z1 = f2fma(f2dup(a0.w), w[3], z1);
        z0 = f2fma(f2dup(a1.x), w[4], z0);  z1 = f2fma(f2dup(a1.y), w[5], z1);
        z0 = f2fma(f2dup(a1.z), w[6], z0);  z1 = f2fma(f2dup(a1.w), w[7], z1);
        z0 = f2fma(f2dup(a2.x), w[8], z0);  z1 = f2fma(f2dup(a2.y), w[9], z1);
        z0 = f2fma(f2dup(a2.z), w[10], z0); z1 = f2fma(f2dup(a2.w), w[11], z1);
        z0 = f2fma(f2dup(a3.x), w[12], z0); z1 = f2fma(f2dup(a3.y), w[13], z1);
        z0 = f2fma(f2dup(a3.z), w[14], z0); z1 = f2fma(f2dup(a3.w), w[15], z1);
        float2 za = f2unpack(z0), zb = f2unpack(z1);
        accx += fmaxf(y0.x + za.x + zb.x, 0.f);
        accy += fmaxf(y0.y + za.y + zb.y, 0.f);
    }
    *reinterpret_cast<float2*>(g_agg + (u64)node * DD + 2 * lane) =
        make_float2(accx, accy);
}

#define UPD_SMEM (128 * 130 * 4 + 128 * 64 * 4)
__global__ __launch_bounds__(256) void k_update(const float* __restrict__ x,
                                                const float* __restrict__ uW,
                                                const float* __restrict__ ub,
                                                float* __restrict__ xo) {
    extern __shared__ float us[];
    float(*sIn)[130] = reinterpret_cast<float(*)[130]>(us);
    float(*sW)[64] = reinterpret_cast<float(*)[64]>(us + 128 * 130);
    int tid = threadIdx.x;
    int node0 = blockIdx.x * 128;
    for (int i = tid; i < 128 * 64; i += 256) sW[i >> 6][i & 63] = uW[i];
    for (int i = tid; i < 128 * 128; i += 256) {
        int n = i >> 7, c = i & 127;
        int nn = node0 + n;
        if (nn >= NN) nn = NN - 1;
        float v = (c < 64) ? x[(u64)nn * DD + c] : g_agg[(u64)nn * DD + c - 64];
        sIn[n][c] = v;
    }
    __syncthreads();
    int f0 = (tid & 7) * 8;
    int n0 = (tid >> 3) * 4;
    u64 acc[4][4];
#pragma unroll
    for (int j = 0; j < 4; j++)
#pragma unroll
        for (int c = 0; c < 4; c++) acc[j][c] = 0ull;
#pragma unroll 8
    for (int k = 0; k < 128; k++) {
        ulonglong2 w01 = *reinterpret_cast<const ulonglong2*>(&sW[k][f0]);
        ulonglong2 w23 = *reinterpret_cast<const ulonglong2*>(&sW[k][f0 + 4]);
#pragma unroll
        for (int j = 0; j < 4; j++) {
            u64 a = f2dup(sIn[n0 + j][k]);
            acc[j][0] = f2fma(a, w01.x, acc[j][0]);
            acc[j][1] = f2fma(a, w01.y, acc[j][1]);
            acc[j][2] = f2fma(a, w23.x, acc[j][2]);
            acc[j][3] = f2fma(a, w23.y, acc[j][3]);
        }
    }
    float2 bv[4];
#pragma unroll
    for (int c = 0; c < 4; c++)
        bv[c] = *reinterpret_cast<const float2*>(ub + f0 + 2 * c);
#pragma unroll
    for (int j = 0; j < 4; j++) {
        int nn = node0 + n0 + j;
        if (nn < NN) {
            float o[8];
#pragma unroll
            for (int c = 0; c < 4; c++) {
                float2 v = f2unpack(acc[j][c]);
                o[2 * c] = fmaxf(v.x + bv[c].x, 0.f);
                o[2 * c + 1] = fmaxf(v.y + bv[c].y, 0.f);
            }
            float* op = xo + (u64)nn * DD + f0;
            *reinterpret_cast<float4*>(op) = make_float4(o[0], o[1], o[2], o[3]);
            *reinterpret_cast<float4*>(op + 4) = make_float4(o[4], o[5], o[6], o[7]);
        }
    }
}

#define NM_SMEM (64 * 128 * 4 + 64 * 65 * 4 + 64 * 130 * 4 + 128 * 4 * 4)
__global__ __launch_bounds__(256) void k_nodemlp(const float* __restrict__ W1,
                                                 const float* __restrict__ b1,
                                                 const float* __restrict__ W2,
                                                 const float* __restrict__ b2,
                                                 float* __restrict__ out) {
    extern __shared__ float nsm[];
    float(*sW1)[128] = reinterpret_cast<float(*)[128]>(nsm);
    float(*sX)[65] = reinterpret_cast<float(*)[65]>(nsm + 64 * 128);
    float(*sH)[130] = reinterpret_cast<float(*)[130]>(nsm + 64 * 128 + 64 * 65);
    float(*sW2)[4] =
        reinterpret_cast<float(*)[4]>(nsm + 64 * 128 + 64 * 65 + 64 * 130);
    int tid = threadIdx.x;
    int node0 = blockIdx.x * 64;
    for (int i = tid; i < 64 * 128; i += 256) sW1[i >> 7][i & 127] = W1[i];
    if (tid < 128) {
        sW2[tid][0] = W2[tid * 3 + 0];
        sW2[tid][1] = W2[tid * 3 + 1];
        sW2[tid][2] = W2[tid * 3 + 2];
    }
    for (int i = tid; i < 64 * 64; i += 256) {
        int n = i >> 6, c = i & 63;
        int nn = node0 + n;
        if (nn >= NN) nn = NN - 1;
        sX[n][c] = g_x[(u64)nn * DD + c];
    }
    __syncthreads();
    int f0 = (tid & 15) * 8;
    int n0 = (tid >> 4) * 4;
    u64 acc[4][4];
#pragma unroll
    for (int j = 0; j < 4; j++)
#pragma unroll
        for (int c = 0; c < 4; c++) acc[j][c] = 0ull;
#pragma unroll 8
    for (int k = 0; k < 64; k++) {
        ulonglong2 w01 = *reinterpret_cast<const ulonglong2*>(&sW1[k][f0]);
        ulonglong2 w23 = *reinterpret_cast<const ulonglong2*>(&sW1[k][f0 + 4]);
#pragma unroll
        for (int j = 0; j < 4; j++) {
            u64 a = f2dup(sX[n0 + j][k]);
            acc[j][0] = f2fma(a, w01.x, acc[j][0]);
            acc[j][1] = f2fma(a, w01.y, acc[j][1]);
            acc[j][2] = f2fma(a, w23.x, acc[j][2]);
            acc[j][3] = f2fma(a, w23.y, acc[j][3]);
        }
    }
    float2 bv[4];
#pragma unroll
    for (int c = 0; c < 4; c++)
        bv[c] = *reinterpret_cast<const float2*>(b1 + f0 + 2 * c);
#pragma unroll
    for (int j = 0; j < 4; j++) {
#pragma unroll
        for (int c = 0; c < 4; c++) {
            float2 v = f2unpack(acc[j][c]);
            sH[n0 + j][f0 + 2 * c] = fmaxf(v.x + bv[c].x, 0.f);
            sH[n0 + j][f0 + 2 * c + 1] = fmaxf(v.y + bv[c].y, 0.f);
        }
    }
    __syncthreads();
    if (tid < 192) {
        int node = tid / 3, c = tid % 3;
        int nn = node0 + node;
        if (nn < NN) {
            float o = b2[c];
#pragma unroll 16
            for (int j = 0; j < 128; j++) o += sH[node][j] * sW2[j][c];
            out[(u64)nn * 3 + c] = o;
        }
    }
}

extern "C" void kernel_launch(void* const* d_in, const int* in_sizes, int n_in,
                              void* d_out, int out_size) {
    const float* emb = (const float*)d_in[0];
    const int* edge_index = (const int*)d_in[1];
    const float* edge_attr = (const float*)d_in[2];
    const float* Wg1 = (const float*)d_in[3];
    const float* bg1 = (const float*)d_in[4];
    const float* Wg2 = (const float*)d_in[5];
    const float* bg2 = (const float*)d_in[6];
    const float* mW0 = (const float*)d_in[7];
    const float* mb0 = (const float*)d_in[8];
    const float* uW0 = (const float*)d_in[9];
    const float* ub0 = (const float*)d_in[10];
    const float* mW1 = (const float*)d_in[11];
    const float* mb1 = (const float*)d_in[12];
    const float* uW1 = (const float*)d_in[13];
    const float* ub1 = (const float*)d_in[14];
    const float* nW1 = (const float*)d_in[15];
    const float* nb1 = (const float*)d_in[16];
    const float* nW2 = (const float*)d_in[17];
    const float* nb2 = (const float*)d_in[18];
    float* out = (float*)d_out;

    float *p_x, *p_x2;
    cudaGetSymbolAddress((void**)&p_x, g_x);
    cudaGetSymbolAddress((void**)&p_x2, g_x2);

    cudaFuncSetAttribute(k_update, cudaFuncAttributeMaxDynamicSharedMemorySize,
                         UPD_SMEM);
    cudaFuncSetAttribute(k_nodemlp, cudaFuncAttributeMaxDynamicSharedMemorySize,
                         NM_SMEM);

    // profiled launch (#3) = k_mlp2
    k_zero_cnt<<<(NN + 255) / 256, 256>>>();
    k_hist<<<(NE + 255) / 256, 256>>>(edge_index);
    k_mlp1<<<NB, 512>>>(emb, Wg1, bg1);
    k_mlp2<<<G2D / 128, 256>>>(Wg2, bg2);
    k_scan1<<<NSCAN_BLKS, 512>>>();
    k_scan2<<<1, 256>>>();
    k_scan3<<<(NN + 255) / 256, 256>>>();
    k_permgather<<<(NE + 255) / 256, 256>>>(edge_index, edge_attr);

    k_ynode<<<(NN + 63) / 64, 128>>>(p_x, mW0, mb0);
    k_agg<<<NN / 8, 256>>>(mW0);
    k_update<<<(NN + 127) / 128, 256, UPD_SMEM>>>(p_x, uW0, ub0, p_x2);
    k_ynode<<<(NN + 63) / 64, 128>>>(p_x2, mW1, mb1);
    k_agg<<<NN / 8, 256>>>(mW1);
    k_update<<<(NN + 127) / 128, 256, UPD_SMEM>>>(p_x2, uW1, ub1, p_x);
    k_nodemlp<<<(NN + 63) / 64, 256, NM_SMEM>>>(nW1, nb1, nW2, nb2, out);
}